// round 2
// baseline (speedup 1.0000x reference)
#include <cuda_runtime.h>
#include <cuda_bf16.h>
#include <math.h>

#define N_NODES 100000
#define N_EDGES 1600000
#define DIM 128
#define SCAN_BLK 1024
#define NBLK ((N_NODES + SCAN_BLK - 1) / SCAN_BLK)   // 98

// ---------------- scratch (device globals; no allocations allowed) -------------
__device__ int   g_is64;
__device__ int   g_cnt[N_NODES];
__device__ int   g_cur[N_NODES];
__device__ int   g_tmp[N_NODES];
__device__ int   g_blocksum[128];
__device__ int   g_blockoff[128];
__device__ int   g_rowptr[N_NODES + 1];
__device__ int   g_perm[N_EDGES];
__device__ float g_deginv[N_NODES];
__device__ float g_agg[(size_t)N_NODES * DIM];
__device__ float g_h1[(size_t)N_NODES * DIM];
__device__ float g_h2[(size_t)N_NODES * DIM];
__device__ float g_p[N_NODES * 2];
__device__ float g_q[N_NODES * 2];

// ---------------- dtype detection -------------------------------------------
// Values are in [0, 100000). If stored as int64, every odd int32 word of the
// first 8192 entries is 0. A genuine int32 array of random node ids has ~0
// probability of 4096 zeros at odd positions.
__global__ void k_detect(const int* __restrict__ ei32) {
    __shared__ int nz;
    if (threadIdx.x == 0) nz = 0;
    __syncthreads();
    for (int i = threadIdx.x; i < 4096; i += blockDim.x) {
        if (ei32[2 * i + 1] != 0) nz = 1;
    }
    __syncthreads();
    if (threadIdx.x == 0) g_is64 = (nz == 0) ? 1 : 0;
}

__device__ __forceinline__ int load_idx(const void* ei, size_t pos, int is64) {
    if (is64) return (int)((const long long*)ei)[pos];
    return ((const int*)ei)[pos];
}

// ---------------- CSR build --------------------------------------------------
__global__ void k_zero_counts() {
    int i = blockIdx.x * blockDim.x + threadIdx.x;
    if (i < N_NODES) { g_cnt[i] = 0; g_cur[i] = 0; }
}

__global__ void k_hist(const void* __restrict__ ei) {
    int e = blockIdx.x * blockDim.x + threadIdx.x;
    int is64 = g_is64;
    if (e < N_EDGES) {
        int d = load_idx(ei, (size_t)N_EDGES + e, is64);
        atomicAdd(&g_cnt[d], 1);
    }
}

__global__ void k_scan_a() {
    __shared__ int sh[SCAN_BLK];
    int tid = threadIdx.x;
    int i = blockIdx.x * SCAN_BLK + tid;
    int v = (i < N_NODES) ? g_cnt[i] : 0;
    sh[tid] = v;
    __syncthreads();
    for (int off = 1; off < SCAN_BLK; off <<= 1) {
        int t = 0;
        if (tid >= off) t = sh[tid - off];
        __syncthreads();
        if (tid >= off) sh[tid] += t;
        __syncthreads();
    }
    if (i < N_NODES) g_tmp[i] = sh[tid] - v;       // exclusive within block
    if (tid == SCAN_BLK - 1) g_blocksum[blockIdx.x] = sh[tid];
}

__global__ void k_scan_b() {
    __shared__ int sh[128];
    int tid = threadIdx.x;
    int v = (tid < NBLK) ? g_blocksum[tid] : 0;
    sh[tid] = v;
    __syncthreads();
    for (int off = 1; off < 128; off <<= 1) {
        int t = 0;
        if (tid >= off) t = sh[tid - off];
        __syncthreads();
        if (tid >= off) sh[tid] += t;
        __syncthreads();
    }
    if (tid < NBLK) g_blockoff[tid] = sh[tid] - v; // exclusive
}

__global__ void k_scan_c() {
    int i = blockIdx.x * SCAN_BLK + threadIdx.x;
    if (i < N_NODES) {
        g_rowptr[i] = g_tmp[i] + g_blockoff[blockIdx.x];
        int c = g_cnt[i];
        g_deginv[i] = 1.0f / (float)max(c, 1);
    }
    if (i == 0) g_rowptr[N_NODES] = N_EDGES;
}

__global__ void k_perm(const void* __restrict__ ei) {
    int e = blockIdx.x * blockDim.x + threadIdx.x;
    int is64 = g_is64;
    if (e < N_EDGES) {
        int s = load_idx(ei, (size_t)e, is64);
        int d = load_idx(ei, (size_t)N_EDGES + e, is64);
        int pos = g_rowptr[d] + atomicAdd(&g_cur[d], 1);
        g_perm[pos] = s;
    }
}

// ---------------- gather-aggregate (warp per node, lane owns 4 feats) --------
__global__ void k_gather(const float* __restrict__ feat, float* __restrict__ out) {
    int warp = (blockIdx.x * blockDim.x + threadIdx.x) >> 5;
    int lane = threadIdx.x & 31;
    if (warp >= N_NODES) return;
    int s0 = g_rowptr[warp];
    int s1 = g_rowptr[warp + 1];
    float4 acc = make_float4(0.f, 0.f, 0.f, 0.f);
    int e = s0;
    for (; e + 1 < s1; e += 2) {
        int sa = __ldg(&g_perm[e]);
        int sb = __ldg(&g_perm[e + 1]);
        float4 va = *(const float4*)(feat + (size_t)sa * DIM + lane * 4);
        float4 vb = *(const float4*)(feat + (size_t)sb * DIM + lane * 4);
        acc.x += va.x; acc.y += va.y; acc.z += va.z; acc.w += va.w;
        acc.x += vb.x; acc.y += vb.y; acc.z += vb.z; acc.w += vb.w;
    }
    if (e < s1) {
        int sa = __ldg(&g_perm[e]);
        float4 va = *(const float4*)(feat + (size_t)sa * DIM + lane * 4);
        acc.x += va.x; acc.y += va.y; acc.z += va.z; acc.w += va.w;
    }
    float di = g_deginv[warp];
    acc.x *= di; acc.y *= di; acc.z *= di; acc.w *= di;
    *(float4*)(out + (size_t)warp * DIM + lane * 4) = acc;
}

// ---------------- fused GEMM: out = relu([agg_scaled, X] @ [Wl;Wr] + b) ------
#define BM 128
#define BN 128
#define BK 16

__global__ void __launch_bounds__(256, 2)
k_gemm(const float* __restrict__ Aagg, const float* __restrict__ Ax,
       const float* __restrict__ Wl, const float* __restrict__ Wr,
       const float* __restrict__ bias, float* __restrict__ out) {
    __shared__ float As[BK][BM + 4];
    __shared__ float Bs[BK][BN];

    int tid = threadIdx.x;
    int tx = tid & 15;          // col group
    int ty = tid >> 4;          // row group
    int row_base = blockIdx.x * BM;

    float acc[8][8];
#pragma unroll
    for (int i = 0; i < 8; i++)
#pragma unroll
        for (int j = 0; j < 8; j++) acc[i][j] = 0.f;

    for (int step = 0; step < 16; step++) {
        int k0 = step * BK;                    // 0..240
        const float* Asrc = (k0 < 128) ? Aagg : Ax;
        const float* Bsrc = (k0 < 128) ? Wl : Wr;
        int kbase = k0 & 127;

#pragma unroll
        for (int i = 0; i < 2; i++) {
            int f = tid + i * 256;             // 0..511
            int row = f >> 2;                  // 0..127
            int kq = (f & 3) * 4;              // 0,4,8,12
            int gr = row_base + row;
            float4 v = make_float4(0.f, 0.f, 0.f, 0.f);
            if (gr < N_NODES)
                v = *(const float4*)(Asrc + (size_t)gr * DIM + kbase + kq);
            As[kq + 0][row] = v.x;
            As[kq + 1][row] = v.y;
            As[kq + 2][row] = v.z;
            As[kq + 3][row] = v.w;
        }
#pragma unroll
        for (int i = 0; i < 2; i++) {
            int f = tid + i * 256;
            int krow = f >> 5;                 // 0..15
            int nq = (f & 31) * 4;
            *(float4*)&Bs[krow][nq] = *(const float4*)(Bsrc + (size_t)(kbase + krow) * DIM + nq);
        }
        __syncthreads();

#pragma unroll
        for (int kk = 0; kk < BK; kk++) {
            float a[8], b[8];
            float4 a0 = *(float4*)&As[kk][ty * 8];
            float4 a1 = *(float4*)&As[kk][ty * 8 + 4];
            float4 b0 = *(float4*)&Bs[kk][tx * 8];
            float4 b1 = *(float4*)&Bs[kk][tx * 8 + 4];
            a[0]=a0.x; a[1]=a0.y; a[2]=a0.z; a[3]=a0.w;
            a[4]=a1.x; a[5]=a1.y; a[6]=a1.z; a[7]=a1.w;
            b[0]=b0.x; b[1]=b0.y; b[2]=b0.z; b[3]=b0.w;
            b[4]=b1.x; b[5]=b1.y; b[6]=b1.z; b[7]=b1.w;
#pragma unroll
            for (int i = 0; i < 8; i++)
#pragma unroll
                for (int j = 0; j < 8; j++)
                    acc[i][j] = fmaf(a[i], b[j], acc[i][j]);
        }
        __syncthreads();
    }

    float bj[8];
#pragma unroll
    for (int j = 0; j < 8; j++) bj[j] = bias[tx * 8 + j];

#pragma unroll
    for (int i = 0; i < 8; i++) {
        int r = row_base + ty * 8 + i;
        if (r < N_NODES) {
            float v[8];
#pragma unroll
            for (int j = 0; j < 8; j++) v[j] = fmaxf(acc[i][j] + bj[j], 0.f);
            float4 o0 = make_float4(v[0], v[1], v[2], v[3]);
            float4 o1 = make_float4(v[4], v[5], v[6], v[7]);
            *(float4*)(out + (size_t)r * DIM + tx * 8)     = o0;
            *(float4*)(out + (size_t)r * DIM + tx * 8 + 4) = o1;
        }
    }
}

// ---------------- layer-3 pre-projection: p = h2@W3_l, q = h2@W3_r + b3 ------
__global__ void k_pq(const float* __restrict__ W3l, const float* __restrict__ W3r,
                     const float* __restrict__ b3) {
    int warp = (blockIdx.x * blockDim.x + threadIdx.x) >> 5;
    int lane = threadIdx.x & 31;
    if (warp >= N_NODES) return;
    float4 h = *(const float4*)(g_h2 + (size_t)warp * DIM + lane * 4);
    float hv[4] = {h.x, h.y, h.z, h.w};
    float pl0 = 0.f, pl1 = 0.f, pr0 = 0.f, pr1 = 0.f;
#pragma unroll
    for (int j = 0; j < 4; j++) {
        int k = lane * 4 + j;
        pl0 = fmaf(hv[j], __ldg(&W3l[k * 2 + 0]), pl0);
        pl1 = fmaf(hv[j], __ldg(&W3l[k * 2 + 1]), pl1);
        pr0 = fmaf(hv[j], __ldg(&W3r[k * 2 + 0]), pr0);
        pr1 = fmaf(hv[j], __ldg(&W3r[k * 2 + 1]), pr1);
    }
#pragma unroll
    for (int off = 16; off > 0; off >>= 1) {
        pl0 += __shfl_down_sync(0xffffffffu, pl0, off);
        pl1 += __shfl_down_sync(0xffffffffu, pl1, off);
        pr0 += __shfl_down_sync(0xffffffffu, pr0, off);
        pr1 += __shfl_down_sync(0xffffffffu, pr1, off);
    }
    if (lane == 0) {
        g_p[warp * 2 + 0] = pl0;
        g_p[warp * 2 + 1] = pl1;
        g_q[warp * 2 + 0] = pr0 + b3[0];
        g_q[warp * 2 + 1] = pr1 + b3[1];
    }
}

// ---------------- layer-3 gather + relu + log_softmax ------------------------
__global__ void k_final(float* __restrict__ out) {
    int warp = (blockIdx.x * blockDim.x + threadIdx.x) >> 5;
    int lane = threadIdx.x & 31;
    if (warp >= N_NODES) return;
    int s0 = g_rowptr[warp];
    int s1 = g_rowptr[warp + 1];
    float a0 = 0.f, a1 = 0.f;
    for (int e = s0 + lane; e < s1; e += 32) {
        int s = __ldg(&g_perm[e]);
        a0 += g_p[s * 2 + 0];
        a1 += g_p[s * 2 + 1];
    }
#pragma unroll
    for (int off = 16; off > 0; off >>= 1) {
        a0 += __shfl_down_sync(0xffffffffu, a0, off);
        a1 += __shfl_down_sync(0xffffffffu, a1, off);
    }
    if (lane == 0) {
        float di = g_deginv[warp];
        float v0 = fmaxf(a0 * di + g_q[warp * 2 + 0], 0.f);
        float v1 = fmaxf(a1 * di + g_q[warp * 2 + 1], 0.f);
        float m = fmaxf(v0, v1);
        float lse = m + logf(expf(v0 - m) + expf(v1 - m));
        out[warp * 2 + 0] = v0 - lse;
        out[warp * 2 + 1] = v1 - lse;
    }
}

// ---------------- launch -----------------------------------------------------
extern "C" void kernel_launch(void* const* d_in, const int* in_sizes, int n_in,
                              void* d_out, int out_size) {
    const float* x   = (const float*)d_in[0];
    const void*  ei  = d_in[1];
    const float* W1l = (const float*)d_in[2];
    const float* W1r = (const float*)d_in[3];
    const float* b1  = (const float*)d_in[4];
    const float* W2l = (const float*)d_in[5];
    const float* W2r = (const float*)d_in[6];
    const float* b2  = (const float*)d_in[7];
    const float* W3l = (const float*)d_in[8];
    const float* W3r = (const float*)d_in[9];
    const float* b3  = (const float*)d_in[10];
    float* out = (float*)d_out;

    const int EDGE_BLOCKS = (N_EDGES + 255) / 256;
    const int NODE_BLOCKS = (N_NODES + 255) / 256;
    const int WARP_BLOCKS = (N_NODES * 32 + 255) / 256;   // one warp per node
    const int GEMM_BLOCKS = (N_NODES + BM - 1) / BM;

    float* agg; cudaGetSymbolAddress((void**)&agg, g_agg);
    float* h1;  cudaGetSymbolAddress((void**)&h1,  g_h1);
    float* h2;  cudaGetSymbolAddress((void**)&h2,  g_h2);

    // dtype sniff + CSR build
    k_detect<<<1, 256>>>((const int*)ei);
    k_zero_counts<<<NODE_BLOCKS, 256>>>();
    k_hist<<<EDGE_BLOCKS, 256>>>(ei);
    k_scan_a<<<NBLK, SCAN_BLK>>>();
    k_scan_b<<<1, 128>>>();
    k_scan_c<<<NBLK, SCAN_BLK>>>();
    k_perm<<<EDGE_BLOCKS, 256>>>(ei);

    // layer 1
    k_gather<<<WARP_BLOCKS, 256>>>(x, agg);
    k_gemm<<<GEMM_BLOCKS, 256>>>(agg, x, W1l, W1r, b1, h1);

    // layer 2
    k_gather<<<WARP_BLOCKS, 256>>>(h1, agg);
    k_gemm<<<GEMM_BLOCKS, 256>>>(agg, h1, W2l, W2r, b2, h2);

    // layer 3 (projection first, then 2-wide aggregation)
    k_pq<<<WARP_BLOCKS, 256>>>(W3l, W3r, b3);
    k_final<<<WARP_BLOCKS, 256>>>(out);
}

// round 6
// speedup vs baseline: 2.3872x; 2.3872x over previous
#include <cuda_runtime.h>
#include <cuda_bf16.h>
#include <math.h>
#include <stdint.h>

#define N_NODES 100000
#define N_EDGES 1600000
#define DIM 128
#define SCAN_BLK 1024
#define NBLK ((N_NODES + SCAN_BLK - 1) / SCAN_BLK)   // 98

// ---------------- scratch (device globals; no allocations allowed) -------------
__device__ int   g_is64;
__device__ int   g_cnt[N_NODES];
__device__ int   g_cur[N_NODES];
__device__ int   g_tmp[N_NODES];
__device__ int   g_blocksum[128];
__device__ int   g_blockoff[128];
__device__ int   g_rowptr[N_NODES + 1];
__device__ int   g_perm[N_EDGES];
__device__ float g_deginv[N_NODES];
__device__ float g_agg[(size_t)N_NODES * DIM];
__device__ float g_h1[(size_t)N_NODES * DIM];
__device__ float g_h2[(size_t)N_NODES * DIM];
__device__ float g_wt1[128 * 256];
__device__ float g_wt2[128 * 256];
__device__ float g_p[N_NODES * 2];
__device__ float g_q[N_NODES * 2];

__device__ __forceinline__ float cvt_tf32(float x) {
    float r; asm("cvt.rna.tf32.f32 %0, %1;" : "=f"(r) : "f"(x)); return r;
}

// ---------------- dtype detection -------------------------------------------
__global__ void k_detect(const int* __restrict__ ei32) {
    __shared__ int nz;
    if (threadIdx.x == 0) nz = 0;
    __syncthreads();
    for (int i = threadIdx.x; i < 4096; i += blockDim.x)
        if (ei32[2 * i + 1] != 0) nz = 1;
    __syncthreads();
    if (threadIdx.x == 0) g_is64 = (nz == 0) ? 1 : 0;
}

__device__ __forceinline__ int load_idx(const void* ei, size_t pos, int is64) {
    if (is64) return (int)((const long long*)ei)[pos];
    return ((const int*)ei)[pos];
}

// ---------------- CSR build --------------------------------------------------
__global__ void k_zero_counts() {
    int i = blockIdx.x * blockDim.x + threadIdx.x;
    if (i < N_NODES) { g_cnt[i] = 0; g_cur[i] = 0; }
}

__global__ void k_hist(const void* __restrict__ ei) {
    int e = blockIdx.x * blockDim.x + threadIdx.x;
    int is64 = g_is64;
    if (e < N_EDGES) {
        int d = load_idx(ei, (size_t)N_EDGES + e, is64);
        atomicAdd(&g_cnt[d], 1);
    }
}

__global__ void k_scan_a() {
    __shared__ int sh[SCAN_BLK];
    int tid = threadIdx.x;
    int i = blockIdx.x * SCAN_BLK + tid;
    int v = (i < N_NODES) ? g_cnt[i] : 0;
    sh[tid] = v;
    __syncthreads();
    for (int off = 1; off < SCAN_BLK; off <<= 1) {
        int t = 0;
        if (tid >= off) t = sh[tid - off];
        __syncthreads();
        if (tid >= off) sh[tid] += t;
        __syncthreads();
    }
    if (i < N_NODES) g_tmp[i] = sh[tid] - v;
    if (tid == SCAN_BLK - 1) g_blocksum[blockIdx.x] = sh[tid];
}

__global__ void k_scan_b() {
    __shared__ int sh[128];
    int tid = threadIdx.x;
    int v = (tid < NBLK) ? g_blocksum[tid] : 0;
    sh[tid] = v;
    __syncthreads();
    for (int off = 1; off < 128; off <<= 1) {
        int t = 0;
        if (tid >= off) t = sh[tid - off];
        __syncthreads();
        if (tid >= off) sh[tid] += t;
        __syncthreads();
    }
    if (tid < NBLK) g_blockoff[tid] = sh[tid] - v;
}

__global__ void k_scan_c() {
    int i = blockIdx.x * SCAN_BLK + threadIdx.x;
    if (i < N_NODES) {
        g_rowptr[i] = g_tmp[i] + g_blockoff[blockIdx.x];
        int c = g_cnt[i];
        g_deginv[i] = 1.0f / (float)max(c, 1);
    }
    if (i == 0) g_rowptr[N_NODES] = N_EDGES;
}

__global__ void k_perm(const void* __restrict__ ei) {
    int e = blockIdx.x * blockDim.x + threadIdx.x;
    int is64 = g_is64;
    if (e < N_EDGES) {
        int s = load_idx(ei, (size_t)e, is64);
        int d = load_idx(ei, (size_t)N_EDGES + e, is64);
        int pos = g_rowptr[d] + atomicAdd(&g_cur[d], 1);
        g_perm[pos] = s;
    }
}

// ---------------- weight transpose + stack: Wt[n][k] k=0..255 -----------------
__global__ void k_wt(const float* __restrict__ Wl, const float* __restrict__ Wr,
                     float* __restrict__ Wt) {
    int idx = blockIdx.x * blockDim.x + threadIdx.x;
    if (idx < 128 * 128) {
        int k = idx >> 7, n = idx & 127;
        Wt[n * 256 + k]       = Wl[k * 128 + n];
        Wt[n * 256 + 128 + k] = Wr[k * 128 + n];
    }
}

// ---------------- gather-aggregate (warp per node, lane owns 4 feats) --------
__global__ void k_gather(const float* __restrict__ feat, float* __restrict__ out) {
    int warp = (blockIdx.x * blockDim.x + threadIdx.x) >> 5;
    int lane = threadIdx.x & 31;
    if (warp >= N_NODES) return;
    int s0 = g_rowptr[warp];
    int s1 = g_rowptr[warp + 1];
    float4 acc = make_float4(0.f, 0.f, 0.f, 0.f);
    int e = s0;
    for (; e + 1 < s1; e += 2) {
        int sa = __ldg(&g_perm[e]);
        int sb = __ldg(&g_perm[e + 1]);
        float4 va = *(const float4*)(feat + (size_t)sa * DIM + lane * 4);
        float4 vb = *(const float4*)(feat + (size_t)sb * DIM + lane * 4);
        acc.x += va.x; acc.y += va.y; acc.z += va.z; acc.w += va.w;
        acc.x += vb.x; acc.y += vb.y; acc.z += vb.z; acc.w += vb.w;
    }
    if (e < s1) {
        int sa = __ldg(&g_perm[e]);
        float4 va = *(const float4*)(feat + (size_t)sa * DIM + lane * 4);
        acc.x += va.x; acc.y += va.y; acc.z += va.z; acc.w += va.w;
    }
    float di = g_deginv[warp];
    acc.x *= di; acc.y *= di; acc.z *= di; acc.w *= di;
    *(float4*)(out + (size_t)warp * DIM + lane * 4) = acc;
}

// ---------------- tf32 mma.sync GEMM: out = relu([agg,X] @ Wt^T + b) ----------
// CTA: 128(M) x 128(N). 8 warps, 2x4 layout, warp tile 64x32.
// K = 256 in 8 chunks of 32. mma.m16n8k8.tf32.
#define ASTRIDE 36

__device__ __forceinline__ void mma_tf32(float* c, uint32_t a0, uint32_t a1,
                                         uint32_t a2, uint32_t a3,
                                         uint32_t b0, uint32_t b1) {
    asm volatile(
        "mma.sync.aligned.m16n8k8.row.col.f32.tf32.tf32.f32 "
        "{%0,%1,%2,%3}, {%4,%5,%6,%7}, {%8,%9}, {%0,%1,%2,%3};"
        : "+f"(c[0]), "+f"(c[1]), "+f"(c[2]), "+f"(c[3])
        : "r"(a0), "r"(a1), "r"(a2), "r"(a3), "r"(b0), "r"(b1));
}

__global__ void __launch_bounds__(256, 2)
k_gemm_mma(const float* __restrict__ Aagg, const float* __restrict__ Ax,
           const float* __restrict__ Wt, const float* __restrict__ bias,
           float* __restrict__ out) {
    __shared__ float As[128 * ASTRIDE];
    __shared__ float Bs[128 * ASTRIDE];
    __shared__ float sbias[128];

    int tid = threadIdx.x;
    int wid = tid >> 5, lane = tid & 31;
    int g = lane >> 2, t = lane & 3;             // mma group / thread-in-group
    int warp_m = (wid >> 2) * 64;                // 0 or 64
    int warp_n = (wid & 3) * 32;                 // 0,32,64,96
    int row_base = blockIdx.x * 128;

    if (tid < 128) sbias[tid] = bias[tid];

    float acc[4][4][4];
#pragma unroll
    for (int i = 0; i < 4; i++)
#pragma unroll
        for (int j = 0; j < 4; j++)
#pragma unroll
            for (int q = 0; q < 4; q++) acc[i][j][q] = 0.f;

    for (int ch = 0; ch < 8; ch++) {
        int k0 = ch * 32;
        const float* Asrc = (k0 < 128) ? Aagg : Ax;
        int kbase = k0 & 127;
        __syncthreads();
        // load A tile: 128 rows x 32 k (float4 per thread x4)
#pragma unroll
        for (int i = 0; i < 4; i++) {
            int f = tid + i * 256;               // 0..1023
            int row = f >> 3, seg = f & 7;       // seg*4 = k offset
            float4 v = make_float4(0.f, 0.f, 0.f, 0.f);
            int gr = row_base + row;
            if (gr < N_NODES)
                v = *(const float4*)(Asrc + (size_t)gr * DIM + kbase + seg * 4);
            v.x = cvt_tf32(v.x); v.y = cvt_tf32(v.y);
            v.z = cvt_tf32(v.z); v.w = cvt_tf32(v.w);
            *(float4*)(As + row * ASTRIDE + seg * 4) = v;
        }
        // load B tile: 128 n-rows x 32 k
#pragma unroll
        for (int i = 0; i < 4; i++) {
            int f = tid + i * 256;
            int row = f >> 3, seg = f & 7;
            float4 v = *(const float4*)(Wt + (size_t)row * 256 + k0 + seg * 4);
            v.x = cvt_tf32(v.x); v.y = cvt_tf32(v.y);
            v.z = cvt_tf32(v.z); v.w = cvt_tf32(v.w);
            *(float4*)(Bs + row * ASTRIDE + seg * 4) = v;
        }
        __syncthreads();

#pragma unroll
        for (int kk = 0; kk < 4; kk++) {
            int kof = kk * 8;
            uint32_t af[4][4];
#pragma unroll
            for (int mi = 0; mi < 4; mi++) {
                const float* ap = As + (warp_m + mi * 16 + g) * ASTRIDE + kof + t;
                af[mi][0] = __float_as_uint(ap[0]);
                af[mi][1] = __float_as_uint(ap[8 * ASTRIDE]);
                af[mi][2] = __float_as_uint(ap[4]);
                af[mi][3] = __float_as_uint(ap[8 * ASTRIDE + 4]);
            }
            uint32_t bf[4][2];
#pragma unroll
            for (int ni = 0; ni < 4; ni++) {
                const float* bp = Bs + (warp_n + ni * 8 + g) * ASTRIDE + kof + t;
                bf[ni][0] = __float_as_uint(bp[0]);
                bf[ni][1] = __float_as_uint(bp[4]);
            }
#pragma unroll
            for (int mi = 0; mi < 4; mi++)
#pragma unroll
                for (int ni = 0; ni < 4; ni++)
                    mma_tf32(acc[mi][ni], af[mi][0], af[mi][1], af[mi][2], af[mi][3],
                             bf[ni][0], bf[ni][1]);
        }
    }

    // epilogue: bias + relu, direct stores (float2 per c-pair)
#pragma unroll
    for (int mi = 0; mi < 4; mi++) {
        int r0 = row_base + warp_m + mi * 16 + g;
        int r1 = r0 + 8;
#pragma unroll
        for (int ni = 0; ni < 4; ni++) {
            int c0 = warp_n + ni * 8 + t * 2;
            float b0 = sbias[c0], b1 = sbias[c0 + 1];
            if (r0 < N_NODES) {
                float2 v = make_float2(fmaxf(acc[mi][ni][0] + b0, 0.f),
                                       fmaxf(acc[mi][ni][1] + b1, 0.f));
                *(float2*)(out + (size_t)r0 * DIM + c0) = v;
            }
            if (r1 < N_NODES) {
                float2 v = make_float2(fmaxf(acc[mi][ni][2] + b0, 0.f),
                                       fmaxf(acc[mi][ni][3] + b1, 0.f));
                *(float2*)(out + (size_t)r1 * DIM + c0) = v;
            }
        }
    }
}

// ---------------- layer-3 pre-projection: p = h2@W3_l, q = h2@W3_r + b3 ------
__global__ void k_pq(const float* __restrict__ W3l, const float* __restrict__ W3r,
                     const float* __restrict__ b3) {
    int warp = (blockIdx.x * blockDim.x + threadIdx.x) >> 5;
    int lane = threadIdx.x & 31;
    if (warp >= N_NODES) return;
    float4 h = *(const float4*)(g_h2 + (size_t)warp * DIM + lane * 4);
    float hv[4] = {h.x, h.y, h.z, h.w};
    float pl0 = 0.f, pl1 = 0.f, pr0 = 0.f, pr1 = 0.f;
#pragma unroll
    for (int j = 0; j < 4; j++) {
        int k = lane * 4 + j;
        pl0 = fmaf(hv[j], __ldg(&W3l[k * 2 + 0]), pl0);
        pl1 = fmaf(hv[j], __ldg(&W3l[k * 2 + 1]), pl1);
        pr0 = fmaf(hv[j], __ldg(&W3r[k * 2 + 0]), pr0);
        pr1 = fmaf(hv[j], __ldg(&W3r[k * 2 + 1]), pr1);
    }
#pragma unroll
    for (int off = 16; off > 0; off >>= 1) {
        pl0 += __shfl_down_sync(0xffffffffu, pl0, off);
        pl1 += __shfl_down_sync(0xffffffffu, pl1, off);
        pr0 += __shfl_down_sync(0xffffffffu, pr0, off);
        pr1 += __shfl_down_sync(0xffffffffu, pr1, off);
    }
    if (lane == 0) {
        g_p[warp * 2 + 0] = pl0;
        g_p[warp * 2 + 1] = pl1;
        g_q[warp * 2 + 0] = pr0 + b3[0];
        g_q[warp * 2 + 1] = pr1 + b3[1];
    }
}

// ---------------- layer-3 gather + relu + log_softmax ------------------------
__global__ void k_final(float* __restrict__ out) {
    int warp = (blockIdx.x * blockDim.x + threadIdx.x) >> 5;
    int lane = threadIdx.x & 31;
    if (warp >= N_NODES) return;
    int s0 = g_rowptr[warp];
    int s1 = g_rowptr[warp + 1];
    float a0 = 0.f, a1 = 0.f;
    for (int e = s0 + lane; e < s1; e += 32) {
        int s = __ldg(&g_perm[e]);
        a0 += g_p[s * 2 + 0];
        a1 += g_p[s * 2 + 1];
    }
#pragma unroll
    for (int off = 16; off > 0; off >>= 1) {
        a0 += __shfl_down_sync(0xffffffffu, a0, off);
        a1 += __shfl_down_sync(0xffffffffu, a1, off);
    }
    if (lane == 0) {
        float di = g_deginv[warp];
        float v0 = fmaxf(a0 * di + g_q[warp * 2 + 0], 0.f);
        float v1 = fmaxf(a1 * di + g_q[warp * 2 + 1], 0.f);
        float m = fmaxf(v0, v1);
        float lse = m + logf(expf(v0 - m) + expf(v1 - m));
        out[warp * 2 + 0] = v0 - lse;
        out[warp * 2 + 1] = v1 - lse;
    }
}

// ---------------- launch -----------------------------------------------------
extern "C" void kernel_launch(void* const* d_in, const int* in_sizes, int n_in,
                              void* d_out, int out_size) {
    const float* x   = (const float*)d_in[0];
    const void*  ei  = d_in[1];
    const float* W1l = (const float*)d_in[2];
    const float* W1r = (const float*)d_in[3];
    const float* b1  = (const float*)d_in[4];
    const float* W2l = (const float*)d_in[5];
    const float* W2r = (const float*)d_in[6];
    const float* b2  = (const float*)d_in[7];
    const float* W3l = (const float*)d_in[8];
    const float* W3r = (const float*)d_in[9];
    const float* b3  = (const float*)d_in[10];
    float* out = (float*)d_out;

    const int EDGE_BLOCKS = (N_EDGES + 255) / 256;
    const int NODE_BLOCKS = (N_NODES + 255) / 256;
    const int WARP_BLOCKS = (N_NODES * 32 + 255) / 256;
    const int GEMM_BLOCKS = (N_NODES + 127) / 128;     // 782

    float* agg; cudaGetSymbolAddress((void**)&agg, g_agg);
    float* h1;  cudaGetSymbolAddress((void**)&h1,  g_h1);
    float* h2;  cudaGetSymbolAddress((void**)&h2,  g_h2);
    float* wt1; cudaGetSymbolAddress((void**)&wt1, g_wt1);
    float* wt2; cudaGetSymbolAddress((void**)&wt2, g_wt2);

    // dtype sniff + CSR build + weight prep
    k_detect<<<1, 256>>>((const int*)ei);
    k_zero_counts<<<NODE_BLOCKS, 256>>>();
    k_hist<<<EDGE_BLOCKS, 256>>>(ei);
    k_scan_a<<<NBLK, SCAN_BLK>>>();
    k_scan_b<<<1, 128>>>();
    k_scan_c<<<NBLK, SCAN_BLK>>>();
    k_perm<<<EDGE_BLOCKS, 256>>>(ei);
    k_wt<<<(128 * 128 + 255) / 256, 256>>>(W1l, W1r, wt1);
    k_wt<<<(128 * 128 + 255) / 256, 256>>>(W2l, W2r, wt2);

    // layer 1
    k_gather<<<WARP_BLOCKS, 256>>>(x, agg);
    k_gemm_mma<<<GEMM_BLOCKS, 256>>>(agg, x, wt1, b1, h1);

    // layer 2
    k_gather<<<WARP_BLOCKS, 256>>>(h1, agg);
    k_gemm_mma<<<GEMM_BLOCKS, 256>>>(agg, h1, wt2, b2, h2);

    // layer 3 (projection first, then 2-wide aggregation)
    k_pq<<<WARP_BLOCKS, 256>>>(W3l, W3r, b3);
    k_final<<<WARP_BLOCKS, 256>>>(out);
}